// round 14
// baseline (speedup 1.0000x reference)
#include <cuda_runtime.h>

#define BB 32
#define NN 128
#define DD 135
#define ADJ_OFF 7
#define GRID 256
#define NT 512

#define PXP 36             // pitch (words) of pair buffers: 64 kp rows x (32+4)
#define PWP 132            // pitch (words) of w buffers: 64 kp rows x (128+4)
#define OFF_AT 0           // adjT pair [64][PXP]
#define OFF_XT 2304        // x input pair [64][PXP] (agg fp 0-31, ee fp 32-63)
#define OFF_CT 4608        // upd input pair [64][PXP] (cur fp 0-31, msg fp 32-63)
#define OFF_WA 6912        // w buffer A [64][PWP]
#define OFF_WB 15360       // w buffer B [64][PWP]
#define OFF_NM 23808       // 16 norms
#define SMW    23840

__device__ float g_cur[BB * NN * 64];    // [b][jp 64][f*2 + nodeparity]
__device__ float g_Wt[6 * 128 * 64];     // [m][kp 64][f*2 + kparity]
__device__ float g_PQ[BB * NN * 8];
__device__ float g_part[BB * 8 * 64];
__device__ unsigned g_maxbits;
__device__ unsigned g_cnt = 0, g_gen = 0;

__device__ __forceinline__ void cp16(float* dst_smem, const void* src) {
    unsigned d = (unsigned)__cvta_generic_to_shared(dst_smem);
    asm volatile("cp.async.cg.shared.global [%0], [%1], 16;" :: "r"(d), "l"(src));
}
__device__ __forceinline__ void cp_wait_all() {
    asm volatile("cp.async.wait_all;" ::: "memory");
}

// fill [64][PWP] buffer from 2048 contiguous float4 (straight copy + pitch pad)
__device__ __forceinline__ void fill_w_async(float* dst, const float* src, int t) {
    const float4* s = (const float4*)src;
#pragma unroll
    for (int q = 0; q < 4; q++) {
        int i = q * NT + t;
        int kp = i >> 5, c = i & 31;
        cp16(&dst[kp * PWP + c * 4], &s[i]);
    }
}

__device__ __forceinline__ void gbar() {
    __threadfence();
    __syncthreads();
    if (threadIdx.x == 0) {
        volatile unsigned* vg = &g_gen;
        unsigned gen = *vg;
        unsigned a = atomicAdd(&g_cnt, 1u);
        if (a == GRID - 1) {
            atomicExch(&g_cnt, 0u);
            __threadfence();
            atomicAdd(&g_gen, 1u);
        } else {
            while (*vg == gen) __nanosleep(64);
        }
    }
    __threadfence();
    __syncthreads();
}

// collapse k-pair then reduce over ksplit-4 (lane bits 0-1)
__device__ __forceinline__ float cred(unsigned long long v) {
    float lo, hi;
    asm("mov.b64 {%0,%1}, %2;" : "=f"(lo), "=f"(hi) : "l"(v));
    float s = lo + hi;
    s += __shfl_xor_sync(0xffffffffu, s, 1);
    s += __shfl_xor_sync(0xffffffffu, s, 2);
    return s;
}

// res[q][e] = sum_k x[k][rg*4+q] * w[k][fg2*2+e]  (k-pair FFMA2, ksplit 4)
// xp = byte ptr to pair buffer at (kk*PXP + rg*8)*4
// wp = byte ptr to w buffer at (kk*PWP + fg2*4)*4
template <int NK>
__device__ __forceinline__ void gemm_pair(const char* xp, const char* wp,
                                          float res[4][2]) {
    unsigned long long a00 = 0, a01 = 0, a10 = 0, a11 = 0;
    unsigned long long a20 = 0, a21 = 0, a30 = 0, a31 = 0;
#pragma unroll
    for (int i = 0; i < NK; i++) {
        ulonglong2 xa = *(const ulonglong2*)xp;          // q0, q1 k-pairs
        ulonglong2 xb = *(const ulonglong2*)(xp + 16);   // q2, q3
        ulonglong2 wv = *(const ulonglong2*)wp;          // f0, f1 k-pairs
        asm("fma.rn.f32x2 %0, %1, %2, %0;" : "+l"(a00) : "l"(xa.x), "l"(wv.x));
        asm("fma.rn.f32x2 %0, %1, %2, %0;" : "+l"(a01) : "l"(xa.x), "l"(wv.y));
        asm("fma.rn.f32x2 %0, %1, %2, %0;" : "+l"(a10) : "l"(xa.y), "l"(wv.x));
        asm("fma.rn.f32x2 %0, %1, %2, %0;" : "+l"(a11) : "l"(xa.y), "l"(wv.y));
        asm("fma.rn.f32x2 %0, %1, %2, %0;" : "+l"(a20) : "l"(xb.x), "l"(wv.x));
        asm("fma.rn.f32x2 %0, %1, %2, %0;" : "+l"(a21) : "l"(xb.x), "l"(wv.y));
        asm("fma.rn.f32x2 %0, %1, %2, %0;" : "+l"(a30) : "l"(xb.y), "l"(wv.x));
        asm("fma.rn.f32x2 %0, %1, %2, %0;" : "+l"(a31) : "l"(xb.y), "l"(wv.y));
        xp += 4 * PXP * 4;
        wp += 4 * PWP * 4;
    }
    res[0][0] = cred(a00); res[0][1] = cred(a01);
    res[1][0] = cred(a10); res[1][1] = cred(a11);
    res[2][0] = cred(a20); res[2][1] = cred(a21);
    res[3][0] = cred(a30); res[3][1] = cred(a31);
}

__global__ __launch_bounds__(NT, 2)
void k_mpnn(const float* __restrict__ obs,
            const float* __restrict__ W_init,
            const float* __restrict__ W_ee,
            const float* __restrict__ W_ef,
            const float* __restrict__ Wm_g,
            const float* __restrict__ Wu_g,
            const float* __restrict__ Wp,
            const float* __restrict__ Wr,
            const float* __restrict__ br,
            float4* __restrict__ out) {
    extern __shared__ float sm[];
    const int t = threadIdx.x;
    const int bid = blockIdx.x;
    float* s_aT = sm + OFF_AT;
    float* s_xT = sm + OFF_XT;
    float* s_cT = sm + OFF_CT;
    float* s_wa = sm + OFF_WA;
    float* s_wb = sm + OFF_WB;
    float* s_nm = sm + OFF_NM;
    const char* AT = (const char*)s_aT;
    const char* XT = (const char*)s_xT;
    const char* CT = (const char*)s_cT;
    const char* WA = (const char*)s_wa;
    const char* WB = (const char*)s_wb;

    const int b  = bid >> 3;
    const int r0 = (bid & 7) << 4;          // 16-row / 16-col chunk
    const float* ob = obs + b * NN * DD;

    // lane decomposition: kk(4) x fg2(32 f-pairs... 2 f each) x rg(4)
    const int lane = t & 31, warp = t >> 5;
    const int kk = lane & 3;
    const int fg2 = ((warp & 3) << 3) | (lane >> 2);  // 0..31, covers f=2*fg2,+1
    const int rg = warp >> 2;                          // 0..3
    const int xoff = (kk * PXP + rg * 8) * 4;
    const int woff = (kk * PWP + fg2 * 4) * 4;

    // ============ P0: own-chunk norms + weight transpose (pair layout) =====
    {
        float* part = sm;                   // [16][33] scratch (aT region)
        int c = t & 15, iq = t >> 4;
        const float* o = ob + ADJ_OFF + r0 + c;
        float s = 0.f;
#pragma unroll
        for (int i = iq * 4; i < iq * 4 + 4; i++)
            s += (o[i * DD] != 0.0f) ? 1.0f : 0.0f;
        part[c * 33 + iq] = s;
        __syncthreads();
        if (t < 16) {
            float cnt = 0.f;
#pragma unroll 8
            for (int q = 0; q < 32; q++) cnt += part[t * 33 + q];
            s_nm[t] = (cnt == 0.f) ? 1.0f : cnt;
        }
        __syncthreads();
        if (t == 0) {
            float mx = s_nm[0];
#pragma unroll
            for (int q = 1; q < 16; q++) mx = fmaxf(mx, s_nm[q]);
            atomicMax(&g_maxbits, __float_as_uint(mx));
        }
        if (bid < 48) {
            int m = bid >> 3, seg = bid & 7;
            const float* src = (m & 1) ? (Wu_g + (m >> 1) * 8192)
                                       : (Wm_g + (m >> 1) * 8192);
            float* dst = g_Wt + m * 8192;
            for (int i = seg * 1024 + t; i < seg * 1024 + 1024; i += NT) {
                int f = i >> 7, k = i & 127;    // src [f][k]
                __stcg(&dst[(k >> 1) * 128 + f * 2 + (k & 1)], src[i]);
            }
        }
    }
    gbar();

    const float inv_max = 1.0f / __uint_as_float(__ldcg(&g_maxbits));

    // prefetch Wm(layer 0) -> wB, hidden behind all of P1
    fill_w_async(s_wb, g_Wt, t);

    // ============ P1: adjT + edge stage + init embedding ===================
    {
        float* s_wee = s_xT;            // [0..511]  63x8 zero-padded
        float* s_nf  = s_xT + 512;      // [512..1535]  [j][8]
        float* s_wi  = s_xT + 1536;     // [1536..2047]
        float* s_c   = s_wa;            // [128][66] edge constants
        // esT (pair layout, fp 0..31) aliases s_xT after scratch dead

        for (int i = t; i < 2048; i += NT) {       // adjT pair layout
            int r = i >> 7, j = i & 127;
            s_aT[(j >> 1) * PXP + r * 2 + (j & 1)] = ob[(r0 + r) * DD + ADJ_OFF + j];
        }
        if (t < 512) s_wee[t] = (t < 504) ? W_ee[t] : 0.f;
        for (int i = t; i < 1024; i += NT) {
            int j = i >> 3, d = i & 7;
            s_nf[i] = (d < 7) ? ob[j * DD + d] : 0.f;
        }
        if (t < 512) {
            int f = t >> 3, d = t & 7;
            s_wi[t] = (d < 7) ? W_init[f * 7 + d] : 0.f;
        }
        __syncthreads();

        // edge constant c[j][k] = W_ee[k][1:8] . nf[j]  (reg-cached W row)
        {
            int k = t & 63, jq = t >> 6;
            const float* wr = s_wee + k * 8;
            float w1 = wr[1], w2 = wr[2], w3 = wr[3], w4 = wr[4];
            float w5 = wr[5], w6 = wr[6], w7 = wr[7];
            bool ok = (k < 63);
            for (int j = jq * 16; j < jq * 16 + 16; j++) {
                float4 na = *(const float4*)&s_nf[j * 8];
                float4 nb = *(const float4*)&s_nf[j * 8 + 4];
                float c = w1 * na.x;
                c = fmaf(w2, na.y, c); c = fmaf(w3, na.z, c);
                c = fmaf(w4, na.w, c); c = fmaf(w5, nb.x, c);
                c = fmaf(w6, nb.y, c); c = fmaf(w7, nb.z, c);
                s_c[j * 66 + k] = ok ? c : 0.f;
            }
        }
        // init embedding (own 16 rows) -> g_cur (node-pair layout)
        {
            int f = t & 63, rq = t >> 6;
            const float* wr = s_wi + f * 8;
            float v0 = wr[0], v1 = wr[1], v2 = wr[2], v3 = wr[3];
            float v4 = wr[4], v5 = wr[5], v6 = wr[6];
            for (int r = rq; r < 16; r += 8) {
                int node = r0 + r;
                float4 na = *(const float4*)&s_nf[node * 8];
                float4 nb = *(const float4*)&s_nf[node * 8 + 4];
                float e = v0 * na.x;
                e = fmaf(v1, na.y, e); e = fmaf(v2, na.z, e);
                e = fmaf(v3, na.w, e); e = fmaf(v4, nb.x, e);
                e = fmaf(v5, nb.y, e); e = fmaf(v6, nb.z, e);
                __stcg(&g_cur[b * 8192 + (node >> 1) * 128 + f * 2 + (node & 1)],
                       fmaxf(e, 0.f));
            }
        }
        __syncthreads();

        // edge sum: warp = row, lane = f-pair; write esT (pair layout)
        {
            int r = warp;                    // 0..15
            int f0 = lane << 1;              // 0,2,..62
            float w0a = s_wee[f0 * 8];
            float w0b = s_wee[(f0 + 1) * 8];
            float nrm = s_nm[r];
            __syncthreads();                 // scratch (wee/nf/wi) dead below
            float ax = 0.f, ay = 0.f;
            const float* cp = s_c + f0;
#pragma unroll 4
            for (int j = 0; j < NN; j++) {
                float a = s_aT[(j >> 1) * PXP + r * 2 + (j & 1)];
                if (a != 0.f) {
                    float2 c = *(const float2*)(cp + j * 66);
                    ax += fmaxf(fmaf(a, w0a, c.x), 0.f);
                    ay += fmaxf(fmaf(a, w0b, c.y), 0.f);
                }
            }
            float inv = 1.0f / nrm;
            float2 es;
            es.x = ax * inv;
            es.y = (lane == 31) ? (nrm * inv_max) : ay * inv;
            *(float2*)&s_xT[lane * PXP + r * 2] = es;   // esT fp=lane
        }
        __syncthreads();

        // W_ef -> wA (pair layout, kp rows 0..31)
        for (int i = t; i < 4096; i += NT) {
            int f = i >> 6, k = i & 63;
            s_wa[(k >> 1) * PWP + f * 2 + (k & 1)] = W_ef[i];
        }
        __syncthreads();

        // ee = relu(es @ W_ef^T) -> xT fp rows 32..63
        {
            float res[4][2];
            gemm_pair<8>(XT + xoff, WA + woff, res);
            if (kk == 0) {
#pragma unroll
                for (int q = 0; q < 4; q++) {
                    float2 v;
                    v.x = fmaxf(res[q][0], 0.f);
                    v.y = fmaxf(res[q][1], 0.f);
                    *(float2*)&s_xT[(32 + fg2) * PXP + (rg * 4 + q) * 2] = v;
                }
            }
        }
    }
    gbar();

    // ============ layers ===================================================
    for (int l = 0; l < 3; l++) {
        // cur -> wA (pair layout straight copy)
        fill_w_async(s_wa, g_cur + b * 8192, t);
        cp_wait_all();
        __syncthreads();                                   // sync#1

        // S1: agg = adj @ cur / norm -> xT fp rows 0..31
        {
            float res[4][2];
            gemm_pair<16>(AT + xoff, WA + woff, res);
            if (kk == 0) {
#pragma unroll
                for (int q = 0; q < 4; q++) {
                    float inv = 1.0f / s_nm[rg * 4 + q];
                    float2 v = make_float2(res[q][0] * inv, res[q][1] * inv);
                    *(float2*)&s_xT[fg2 * PXP + (rg * 4 + q) * 2] = v;
                }
            }
        }
        // curT (own 16 rows) -> cT fp rows 0..31 (reads wA node-pair layout)
        for (int i = t; i < 1024; i += NT) {
            int f = i >> 4, r = i & 15;
            int node = r0 + r;
            float c = s_wa[(node >> 1) * PWP + f * 2 + (node & 1)];
            s_cT[(f >> 1) * PXP + r * 2 + (f & 1)] = c;
        }
        __syncthreads();                                   // sync#2

        // Wu -> wA (async, hidden behind S2 gemm)
        fill_w_async(s_wa, g_Wt + (l * 2 + 1) * 8192, t);

        // S2: msg = relu([agg|ee] @ Wm^T) -> cT fp rows 32..63
        {
            float res[4][2];
            gemm_pair<16>(XT + xoff, WB + woff, res);
            cp_wait_all();
            if (kk == 0) {
#pragma unroll
                for (int q = 0; q < 4; q++) {
                    float2 v;
                    v.x = fmaxf(res[q][0], 0.f);
                    v.y = fmaxf(res[q][1], 0.f);
                    *(float2*)&s_cT[(32 + fg2) * PXP + (rg * 4 + q) * 2] = v;
                }
            }
        }
        __syncthreads();                                   // sync#3

        // next layer's Wm -> wB (async, hidden behind S3 gemm)
        if (l < 2) fill_w_async(s_wb, g_Wt + ((l + 1) * 2) * 8192, t);

        // S3: cur' = relu([cur|msg] @ Wu^T)
        {
            float res[4][2];
            gemm_pair<16>(CT + xoff, WA + woff, res);
            if (l < 2) {
                if (kk == 0) {
                    // g_cur node-pair layout: pack along q (node parity)
                    int jp0 = (r0 + rg * 4) >> 1;
#pragma unroll
                    for (int e = 0; e < 2; e++) {
                        int f = fg2 * 2 + e;
                        float2 v01, v23;
                        v01.x = fmaxf(res[0][e], 0.f);
                        v01.y = fmaxf(res[1][e], 0.f);
                        v23.x = fmaxf(res[2][e], 0.f);
                        v23.y = fmaxf(res[3][e], 0.f);
                        __stcg((float2*)&g_cur[b * 8192 + jp0 * 128 + f * 2], v01);
                        __stcg((float2*)&g_cur[b * 8192 + (jp0 + 1) * 128 + f * 2], v23);
                    }
                }
            } else {
                if (kk == 0) {
#pragma unroll
                    for (int q = 0; q < 4; q++) {
                        float2 v;
                        v.x = fmaxf(res[q][0], 0.f);
                        v.y = fmaxf(res[q][1], 0.f);
                        *(float2*)&s_xT[fg2 * PXP + (rg * 4 + q) * 2] = v;
                    }
                }
            }
        }
        if (l < 2) { cp_wait_all(); gbar(); continue; }

        // ---- L3 tail: PQ + pool partials from smem cur' (pair layout) -----
        __syncthreads();
        {
            float* s_wr = s_cT;                 // [8][65]
            for (int i = t; i < 512; i += NT) {
                int c = i >> 6, f = i & 63;
                int oo = c & 3, base = (c >= 4) ? 128 : 64;
                s_wr[c * 65 + f] = Wr[oo * 192 + base + f];
            }
            __syncthreads();
            if (t < 128) {                      // PQ: thread = (i, c)
                int i = t >> 3, c = t & 7;
                float acc = 0.f;
#pragma unroll 8
                for (int f = 0; f < 64; f++)
                    acc = fmaf(s_wr[c * 65 + f],
                               s_xT[(f >> 1) * PXP + i * 2 + (f & 1)], acc);
                __stcg(&g_PQ[(b * NN + r0 + i) * 8 + c], acc);
            } else if (t < 192) {               // pool partial: f = t-128
                int f = t - 128;
                float s = 0.f;
#pragma unroll
                for (int r = 0; r < 16; r++)
                    s += s_xT[(f >> 1) * PXP + r * 2 + (f & 1)];
                __stcg(&g_part[(b * 8 + (bid & 7)) * 64 + f], s);
            }
        }
        gbar();
    }

    // ============ P5: pool reduce + Abias (redundant) + output =============
    {
        float4* sQ = (float4*)sm;              // 128 (aT region dead)
        float4* sP = sQ + 128;                 // 16
        if (t < 128) cp16((float*)&sQ[t], &g_PQ[(b * NN + t) * 8 + 4]);
        else if (t < 144) cp16((float*)&sP[t - 128], &g_PQ[(b * NN + r0 + (t - 128)) * 8]);

        float* s_pool = s_cT;                  // 64
        float* s_rhp  = s_cT + 64;             // 64
        float* s_A    = s_cT + 128;            // 4
        if (t < 64) {
            float s = 0.f;
#pragma unroll
            for (int ch = 0; ch < 8; ch++)
                s += __ldcg(&g_part[(b * 8 + ch) * 64 + t]);
            s_pool[t] = s * (1.0f / 128.0f);
        }
        __syncthreads();
        if (t < 64) {
            float acc = 0.f;
#pragma unroll 8
            for (int g = 0; g < 64; g++) acc = fmaf(Wp[t * 64 + g], s_pool[g], acc);
            s_rhp[t] = fmaxf(acc, 0.f);
        }
        __syncthreads();
        if (t < 4) {
            float acc = br[t];
#pragma unroll 8
            for (int f = 0; f < 64; f++) acc = fmaf(Wr[t * 192 + f], s_rhp[f], acc);
            s_A[t] = acc;
        }
        cp_wait_all();
        __syncthreads();
        float4 A = *(float4*)s_A;
        int i = r0 + (t >> 5), j0 = (t & 31) << 2;
        float4 P = sP[t >> 5];
        float px = A.x + P.x, py = A.y + P.y, pz = A.z + P.z, pw = A.w + P.w;
        float4* op = out + ((b * NN + i) * NN + j0);
#pragma unroll
        for (int j = 0; j < 4; j++) {
            float4 Q = sQ[j0 + j];
            op[j] = make_float4(px + Q.x, py + Q.y, pz + Q.z, pw + Q.w);
        }
    }
}

// ---------------- host launcher --------------------------------------------
extern "C" void kernel_launch(void* const* d_in, const int* in_sizes, int n_in,
                              void* d_out, int out_size) {
    const float* obs    = (const float*)d_in[0];
    const float* W_init = (const float*)d_in[1];
    const float* W_ee   = (const float*)d_in[2];
    const float* W_ef   = (const float*)d_in[3];
    const float* W_msg  = (const float*)d_in[4];
    const float* W_upd  = (const float*)d_in[5];
    const float* W_pool = (const float*)d_in[6];
    const float* W_read = (const float*)d_in[7];
    const float* b_read = (const float*)d_in[8];

    cudaFuncSetAttribute(k_mpnn, cudaFuncAttributeMaxDynamicSharedMemorySize,
                         SMW * 4);
    k_mpnn<<<GRID, NT, SMW * 4>>>(obs, W_init, W_ee, W_ef,
                                  W_msg, W_upd, W_pool, W_read, b_read,
                                  (float4*)d_out);
}

// round 17
// speedup vs baseline: 1.1176x; 1.1176x over previous
#include <cuda_runtime.h>

#define BB 32
#define NN 128
#define DD 135
#define ADJ_OFF 7
#define GRID 256
#define NT 512

#define PX 20              // pitch of transposed [k][16-row] buffers
#define PW 68              // pitch of [k][64-col] buffers
#define OFF_AT 0           // adjT [128][PX] (persistent)
#define OFF_XT 2560        // x input  [128][PX] (agg rows 0-63, ee rows 64-127)
#define OFF_CT 5120        // upd input [128][PX] (curT 0-63, msgT 64-127) / scratch
#define OFF_WA 7680        // buffer A [128][PW]: cur / Wu / edge-c / W_ef
#define OFF_WB 16384       // buffer B [128][PW]: Wm
#define OFF_NM 25088       // 16 norms + 16 rowsums
#define OFF_CS 25120       // 64 colsums
#define SMW    25184

__device__ float g_cur[BB * NN * 64];
__device__ float g_Wt[6 * 128 * 64];     // transposed W_msg/W_upd [m][k][f]
__device__ float g_PQ[BB * NN * 8];
__device__ float g_part[BB * 8 * 64];    // pool partials per (b, chunk)
__device__ unsigned g_maxbits;           // bits of max norm (pos floats)
__device__ unsigned g_cnt = 0, g_gen = 0;

__device__ __forceinline__ void cp16(float* dst_smem, const void* src) {
    unsigned d = (unsigned)__cvta_generic_to_shared(dst_smem);
    asm volatile("cp.async.cg.shared.global [%0], [%1], 16;" :: "r"(d), "l"(src));
}
__device__ __forceinline__ void cp_wait_all() {
    asm volatile("cp.async.wait_all;" ::: "memory");
}

// fill [128][PW]-layout buffer from 2048 contiguous float4 (async)
__device__ __forceinline__ void fill_w_async(float* dst, const float* src, int t) {
    const float4* s = (const float4*)src;
#pragma unroll
    for (int q = 0; q < 4; q++) {
        int i = q * NT + t;
        int k = i >> 4, c = i & 15;
        cp16(&dst[k * PW + c * 4], &s[i]);
    }
}

__device__ __forceinline__ void gbar() {
    __threadfence();
    __syncthreads();
    if (threadIdx.x == 0) {
        volatile unsigned* vg = &g_gen;
        unsigned gen = *vg;
        unsigned a = atomicAdd(&g_cnt, 1u);
        if (a == GRID - 1) {
            atomicExch(&g_cnt, 0u);
            __threadfence();
            atomicAdd(&g_gen, 1u);
        } else {
            while (*vg == gen) __nanosleep(64);
        }
    }
    __threadfence();
    __syncthreads();
}

__device__ __forceinline__ float rsum8(float v) {
    v += __shfl_xor_sync(0xffffffffu, v, 1);
    v += __shfl_xor_sync(0xffffffffu, v, 2);
    v += __shfl_xor_sync(0xffffffffu, v, 4);
    return v;
}

// res[q][e] = sum_k xT[k][rg*4+q] * w[k][fg*4+e]; k-split 8 over lane bits 0-2.
template <int NK>
__device__ __forceinline__ void gemm16(const float* xp, const float* wp,
                                       float res[4][4]) {
    float4 a0 = {0.f, 0.f, 0.f, 0.f}, a1 = a0, a2 = a0, a3 = a0;
#pragma unroll
    for (int i = 0; i < NK; i++) {
        float4 x = *(const float4*)xp;
        float4 w = *(const float4*)wp;
        a0.x = fmaf(x.x, w.x, a0.x); a0.y = fmaf(x.x, w.y, a0.y);
        a0.z = fmaf(x.x, w.z, a0.z); a0.w = fmaf(x.x, w.w, a0.w);
        a1.x = fmaf(x.y, w.x, a1.x); a1.y = fmaf(x.y, w.y, a1.y);
        a1.z = fmaf(x.y, w.z, a1.z); a1.w = fmaf(x.y, w.w, a1.w);
        a2.x = fmaf(x.z, w.x, a2.x); a2.y = fmaf(x.z, w.y, a2.y);
        a2.z = fmaf(x.z, w.z, a2.z); a2.w = fmaf(x.z, w.w, a2.w);
        a3.x = fmaf(x.w, w.x, a3.x); a3.y = fmaf(x.w, w.y, a3.y);
        a3.z = fmaf(x.w, w.z, a3.z); a3.w = fmaf(x.w, w.w, a3.w);
        xp += 8 * PX;
        wp += 8 * PW;
    }
    res[0][0] = rsum8(a0.x); res[0][1] = rsum8(a0.y);
    res[0][2] = rsum8(a0.z); res[0][3] = rsum8(a0.w);
    res[1][0] = rsum8(a1.x); res[1][1] = rsum8(a1.y);
    res[1][2] = rsum8(a1.z); res[1][3] = rsum8(a1.w);
    res[2][0] = rsum8(a2.x); res[2][1] = rsum8(a2.y);
    res[2][2] = rsum8(a2.z); res[2][3] = rsum8(a2.w);
    res[3][0] = rsum8(a3.x); res[3][1] = rsum8(a3.y);
    res[3][2] = rsum8(a3.z); res[3][3] = rsum8(a3.w);
}

__global__ __launch_bounds__(NT, 2)
void k_mpnn(const float* __restrict__ obs,
            const float* __restrict__ W_init,
            const float* __restrict__ W_ee,
            const float* __restrict__ W_ef,
            const float* __restrict__ Wm_g,
            const float* __restrict__ Wu_g,
            const float* __restrict__ Wp,
            const float* __restrict__ Wr,
            const float* __restrict__ br,
            float4* __restrict__ out) {
    extern __shared__ float sm[];
    const int t = threadIdx.x;
    const int bid = blockIdx.x;
    float* s_aT = sm + OFF_AT;
    float* s_xT = sm + OFF_XT;
    float* s_cT = sm + OFF_CT;
    float* s_wa = sm + OFF_WA;
    float* s_wb = sm + OFF_WB;
    float* s_nm = sm + OFF_NM;        // [0..15] norms, [16..31] rowsums
    float* s_cs = sm + OFF_CS;        // [64] colsums of edge-c

    const int b  = bid >> 3;
    const int r0 = (bid & 7) << 4;          // 16-row / 16-col chunk
    const float* ob = obs + b * NN * DD;

    // lane decomposition: kk(8) x fg(16) x rg(4)
    const int lane = t & 31, warp = t >> 5;
    const int kk = lane & 7;
    const int fg = ((warp & 3) << 2) | (lane >> 3);   // 0..15
    const int rg = warp >> 2;                          // 0..3

    // ============ P0: own-chunk norms (all blocks) + weight transpose ======
    {
        float* part = sm;                   // [16][33] scratch (aT region)
        int c = t & 15, iq = t >> 4;        // 32 row-groups of 4
        const float* o = ob + ADJ_OFF + r0 + c;
        float s = 0.f;
#pragma unroll
        for (int i = iq * 4; i < iq * 4 + 4; i++)
            s += (o[i * DD] != 0.0f) ? 1.0f : 0.0f;
        part[c * 33 + iq] = s;
        __syncthreads();
        if (t < 16) {
            float cnt = 0.f;
#pragma unroll 8
            for (int q = 0; q < 32; q++) cnt += part[t * 33 + q];
            s_nm[t] = (cnt == 0.f) ? 1.0f : cnt;
        }
        __syncthreads();
        if (t == 0) {
            float mx = s_nm[0];
#pragma unroll
            for (int q = 1; q < 16; q++) mx = fmaxf(mx, s_nm[q]);
            atomicMax(&g_maxbits, __float_as_uint(mx));
        }
        if (bid < 48) {
            int m = bid >> 3, seg = bid & 7;
            const float* src = (m & 1) ? (Wu_g + (m >> 1) * 8192)
                                       : (Wm_g + (m >> 1) * 8192);
            float* dst = g_Wt + m * 8192;
            for (int i = seg * 1024 + t; i < seg * 1024 + 1024; i += NT) {
                int f = i >> 7, k = i & 127;
                __stcg(&dst[k * 64 + f], src[i]);
            }
        }
    }
    gbar();

    const float inv_max = 1.0f / __uint_as_float(__ldcg(&g_maxbits));

    // prefetch Wm(layer 0) -> wB, hidden behind all of P1
    fill_w_async(s_wb, g_Wt, t);

    // ============ P1: adjT + edge stage + init embedding ===================
    {
        float* s_wee = s_xT;            // [0..511]  63x8 zero-padded
        float* s_nf  = s_xT + 512;      // [512..1535]  [j][8]
        float* s_wi  = s_xT + 1536;     // [1536..2047]
        float* s_c   = s_wa;            // [128][66] edge constants
        float* s_pcs = s_cT;            // [8][64] colsum partials (cT free in P1)
        float* s_rs  = s_nm + 16;       // [16] adj rowsums
        // esT aliases s_xT after scratch dead

        for (int i = t; i < 2048; i += NT) {       // adjT (persistent, 16 rows)
            int r = i >> 7, j = i & 127;
            s_aT[j * PX + r] = ob[(r0 + r) * DD + ADJ_OFF + j];
        }
        if (t < 512) s_wee[t] = (t < 504) ? W_ee[t] : 0.f;
        for (int i = t; i < 1024; i += NT) {
            int j = i >> 3, d = i & 7;
            s_nf[i] = (d < 7) ? ob[j * DD + d] : 0.f;
        }
        if (t < 512) {
            int f = t >> 3, d = t & 7;
            s_wi[t] = (d < 7) ? W_init[f * 7 + d] : 0.f;
        }
        __syncthreads();

        // edge constant c[j][k] = W_ee[k][1:8] . nf[j]  (+ per-thread colsum)
        {
            int k = t & 63, jq = t >> 6;
            const float* wr = s_wee + k * 8;
            float w1 = wr[1], w2 = wr[2], w3 = wr[3], w4 = wr[4];
            float w5 = wr[5], w6 = wr[6], w7 = wr[7];
            bool ok = (k < 63);
            float psum = 0.f;
            for (int j = jq * 16; j < jq * 16 + 16; j++) {
                float4 na = *(const float4*)&s_nf[j * 8];
                float4 nb = *(const float4*)&s_nf[j * 8 + 4];
                float c = w1 * na.x;
                c = fmaf(w2, na.y, c); c = fmaf(w3, na.z, c);
                c = fmaf(w4, na.w, c); c = fmaf(w5, nb.x, c);
                c = fmaf(w6, nb.y, c); c = fmaf(w7, nb.z, c);
                c = ok ? c : 0.f;
                s_c[j * 66 + k] = c;
                psum += c;
            }
            s_pcs[jq * 64 + k] = psum;
        }
        // init embedding (own 16 rows) -> g_cur  (reg-cached W_init row)
        {
            int f = t & 63, rq = t >> 6;
            const float* wr = s_wi + f * 8;
            float v0 = wr[0], v1 = wr[1], v2 = wr[2], v3 = wr[3];
            float v4 = wr[4], v5 = wr[5], v6 = wr[6];
            for (int r = rq; r < 16; r += 8) {
                float4 na = *(const float4*)&s_nf[(r0 + r) * 8];
                float4 nb = *(const float4*)&s_nf[(r0 + r) * 8 + 4];
                float e = v0 * na.x;
                e = fmaf(v1, na.y, e); e = fmaf(v2, na.z, e);
                e = fmaf(v3, na.w, e); e = fmaf(v4, nb.x, e);
                e = fmaf(v5, nb.y, e); e = fmaf(v6, nb.z, e);
                __stcg(&g_cur[(b * NN + r0 + r) * 64 + f], fmaxf(e, 0.f));
            }
        }
        // adj rowsum: warp = row, lane sums 4 cols, warp-reduce
        {
            int r = warp;
            float s = s_aT[lane * PX + r] + s_aT[(lane + 32) * PX + r]
                    + s_aT[(lane + 64) * PX + r] + s_aT[(lane + 96) * PX + r];
            s += __shfl_xor_sync(0xffffffffu, s, 1);
            s += __shfl_xor_sync(0xffffffffu, s, 2);
            s += __shfl_xor_sync(0xffffffffu, s, 4);
            s += __shfl_xor_sync(0xffffffffu, s, 8);
            s += __shfl_xor_sync(0xffffffffu, s, 16);
            if (lane == 0) s_rs[r] = s;
        }
        __syncthreads();

        // colsum reduce: s_cs[k] = sum over 8 partials
        if (t < 64) {
            float s = 0.f;
#pragma unroll
            for (int q = 0; q < 8; q++) s += s_pcs[q * 64 + t];
            s_cs[t] = s;
        }
        __syncthreads();

        // edge sum via relu(x) = 0.5*(x + |x|):
        //   es_f = 0.5*(w_f*rowsum + colsum_f + sum_j |a*w_f + c|) / norm
        {
            int r = warp;                    // 0..15
            int f0 = lane << 1;              // 0,2,..62
            float w0a = s_wee[f0 * 8];
            float w0b = s_wee[(f0 + 1) * 8];
            float nrm = s_nm[r];
            __syncthreads();                 // scratch (wee/nf/wi) dead below
            float rs = s_rs[r];
            float2 cs = *(const float2*)&s_cs[f0];
            float ax = 0.f, ay = 0.f;
            const float* cp = s_c + f0;
            const float* ap = s_aT + r;
#pragma unroll 4
            for (int j = 0; j < NN; j++) {
                float a = ap[j * PX];
                float2 c = *(const float2*)(cp + j * 66);
                ax += fabsf(fmaf(a, w0a, c.x));
                ay += fabsf(fmaf(a, w0b, c.y));
            }
            float inv = 0.5f / nrm;
            s_xT[f0 * PX + r] = (fmaf(w0a, rs, cs.x) + ax) * inv;
            s_xT[(f0 + 1) * PX + r] = (lane == 31)
                ? (nrm * inv_max)
                : (fmaf(w0b, rs, cs.y) + ay) * inv;
        }
        __syncthreads();

        // W_ef^T -> wA (overwrites c)
        for (int i = t; i < 4096; i += NT) {
            int f = i >> 6, k = i & 63;
            s_wa[k * PW + f] = W_ef[i];
        }
        __syncthreads();

        // ee = relu(es @ W_ef^T) -> xT rows 64..127 (transposed)
        {
            float res[4][4];
            gemm16<8>(s_xT + kk * PX + rg * 4, s_wa + kk * PW + fg * 4, res);
            if (kk == 0) {
#pragma unroll
                for (int e = 0; e < 4; e++) {
                    float4 v;
                    v.x = fmaxf(res[0][e], 0.f);
                    v.y = fmaxf(res[1][e], 0.f);
                    v.z = fmaxf(res[2][e], 0.f);
                    v.w = fmaxf(res[3][e], 0.f);
                    *(float4*)&s_xT[(64 + fg * 4 + e) * PX + rg * 4] = v;
                }
            }
        }
    }
    gbar();

    // ============ layers ===================================================
    for (int l = 0; l < 3; l++) {
        // cur -> wA (Wm for this layer already in wB via prefetch)
        fill_w_async(s_wa, g_cur + b * 8192, t);
        cp_wait_all();
        __syncthreads();                                   // sync#1

        // S1: agg = adj @ cur / norm -> xT rows 0..63 (transposed)
        {
            float res[4][4];
            gemm16<16>(s_aT + kk * PX + rg * 4, s_wa + kk * PW + fg * 4, res);
            if (kk == 0) {
                float i0 = 1.0f / s_nm[rg * 4 + 0];
                float i1 = 1.0f / s_nm[rg * 4 + 1];
                float i2 = 1.0f / s_nm[rg * 4 + 2];
                float i3 = 1.0f / s_nm[rg * 4 + 3];
#pragma unroll
                for (int e = 0; e < 4; e++) {
                    float4 v = make_float4(res[0][e] * i0, res[1][e] * i1,
                                           res[2][e] * i2, res[3][e] * i3);
                    *(float4*)&s_xT[(fg * 4 + e) * PX + rg * 4] = v;
                }
            }
        }
        // curT (own 16 rows) -> cT rows 0..63 (reads wA)
        for (int i = t; i < 1024; i += NT) {
            int f = i >> 4, r = i & 15;
            s_cT[f * PX + r] = s_wa[(r0 + r) * PW + f];
        }
        __syncthreads();                                   // sync#2

        // Wu -> wA (async, hidden behind S2 gemm)
        fill_w_async(s_wa, g_Wt + (l * 2 + 1) * 8192, t);

        // S2: msg = relu([agg|ee] @ Wm^T) -> cT rows 64..127
        {
            float res[4][4];
            gemm16<16>(s_xT + kk * PX + rg * 4, s_wb + kk * PW + fg * 4, res);
            cp_wait_all();
            if (kk == 0) {
#pragma unroll
                for (int e = 0; e < 4; e++) {
                    float4 v;
                    v.x = fmaxf(res[0][e], 0.f);
                    v.y = fmaxf(res[1][e], 0.f);
                    v.z = fmaxf(res[2][e], 0.f);
                    v.w = fmaxf(res[3][e], 0.f);
                    *(float4*)&s_cT[(64 + fg * 4 + e) * PX + rg * 4] = v;
                }
            }
        }
        __syncthreads();                                   // sync#3

        // next layer's Wm -> wB (async, hidden behind S3 gemm)
        if (l < 2) fill_w_async(s_wb, g_Wt + ((l + 1) * 2) * 8192, t);

        // S3: cur' = relu([cur|msg] @ Wu^T)
        {
            float res[4][4];
            gemm16<16>(s_cT + kk * PX + rg * 4, s_wa + kk * PW + fg * 4, res);
            if (l < 2) {
                if (kk == 0) {
#pragma unroll
                    for (int q = 0; q < 4; q++) {
                        float4 o;
                        o.x = fmaxf(res[q][0], 0.f);
                        o.y = fmaxf(res[q][1], 0.f);
                        o.z = fmaxf(res[q][2], 0.f);
                        o.w = fmaxf(res[q][3], 0.f);
                        __stcg((float4*)&g_cur[(b * NN + r0 + rg * 4 + q) * 64 + fg * 4], o);
                    }
                }
            } else {
                if (kk == 0) {
#pragma unroll
                    for (int e = 0; e < 4; e++) {
                        float4 v;
                        v.x = fmaxf(res[0][e], 0.f);
                        v.y = fmaxf(res[1][e], 0.f);
                        v.z = fmaxf(res[2][e], 0.f);
                        v.w = fmaxf(res[3][e], 0.f);
                        *(float4*)&s_xT[(fg * 4 + e) * PX + rg * 4] = v;
                    }
                }
            }
        }
        if (l < 2) { cp_wait_all(); gbar(); continue; }

        // ---- L3 tail: PQ + pool partials from smem cur' -------------------
        __syncthreads();
        {
            float* s_wr = s_cT;                 // [8][65]
            for (int i = t; i < 512; i += NT) {
                int c = i >> 6, f = i & 63;
                int oo = c & 3, base = (c >= 4) ? 128 : 64;
                s_wr[c * 65 + f] = Wr[oo * 192 + base + f];
            }
            __syncthreads();
            if (t < 128) {                      // PQ: thread = (i, c)
                int i = t >> 3, c = t & 7;
                float acc = 0.f;
#pragma unroll 8
                for (int f = 0; f < 64; f++)
                    acc = fmaf(s_wr[c * 65 + f], s_xT[f * PX + i], acc);
                __stcg(&g_PQ[(b * NN + r0 + i) * 8 + c], acc);
            } else if (t < 192) {               // pool partial: f = t-128
                int f = t - 128;
                float s = 0.f;
#pragma unroll
                for (int r = 0; r < 16; r++) s += s_xT[f * PX + r];
                __stcg(&g_part[(b * 8 + (bid & 7)) * 64 + f], s);
            }
        }
        gbar();
    }

    // ============ P5: pool reduce + Abias (redundant) + output =============
    {
        float4* sQ = (float4*)sm;              // 128 (aT region dead)
        float4* sP = sQ + 128;                 // 16
        if (t < 128) cp16((float*)&sQ[t], &g_PQ[(b * NN + t) * 8 + 4]);
        else if (t < 144) cp16((float*)&sP[t - 128], &g_PQ[(b * NN + r0 + (t - 128)) * 8]);

        float* s_pool = s_cT;                  // 64
        float* s_rhp  = s_cT + 64;             // 64
        float* s_A    = s_cT + 128;            // 4
        if (t < 64) {
            float s = 0.f;
#pragma unroll
            for (int ch = 0; ch < 8; ch++)
                s += __ldcg(&g_part[(b * 8 + ch) * 64 + t]);
            s_pool[t] = s * (1.0f / 128.0f);
        }
        __syncthreads();
        if (t < 64) {
            float acc = 0.f;
#pragma unroll 8
            for (int g = 0; g < 64; g++) acc = fmaf(Wp[t * 64 + g], s_pool[g], acc);
            s_rhp[t] = fmaxf(acc, 0.f);
        }
        __syncthreads();
        if (t < 4) {
            float acc = br[t];
#pragma unroll 8
            for (int f = 0; f < 64; f++) acc = fmaf(Wr[t * 192 + f], s_rhp[f], acc);
            s_A[t] = acc;
        }
        cp_wait_all();
        __syncthreads();
        float4 A = *(float4*)s_A;
        int i = r0 + (t >> 5), j0 = (t & 31) << 2;
        float4 P = sP[t >> 5];
        float px = A.x + P.x, py = A.y + P.y, pz = A.z + P.z, pw = A.w + P.w;
        float4* op = out + ((b * NN + i) * NN + j0);
#pragma unroll
        for (int j = 0; j < 4; j++) {
            float4 Q = sQ[j0 + j];
            op[j] = make_float4(px + Q.x, py + Q.y, pz + Q.z, pw + Q.w);
        }
    }
}

// ---------------- host launcher --------------------------------------------
extern "C" void kernel_launch(void* const* d_in, const int* in_sizes, int n_in,
                              void* d_out, int out_size) {
    const float* obs    = (const float*)d_in[0];
    const float* W_init = (const float*)d_in[1];
    const float* W_ee   = (const float*)d_in[2];
    const float* W_ef   = (const float*)d_in[3];
    const float* W_msg  = (const float*)d_in[4];
    const float* W_upd  = (const float*)d_in[5];
    const float* W_pool = (const float*)d_in[6];
    const float* W_read = (const float*)d_in[7];
    const float* b_read = (const float*)d_in[8];

    cudaFuncSetAttribute(k_mpnn, cudaFuncAttributeMaxDynamicSharedMemorySize,
                         SMW * 4);
    k_mpnn<<<GRID, NT, SMW * 4>>>(obs, W_init, W_ee, W_ef,
                                  W_msg, W_upd, W_pool, W_read, b_read,
                                  (float4*)d_out);
}